// round 7
// baseline (speedup 1.0000x reference)
#include <cuda_runtime.h>

// MPA_37056977830474 — M=4, F=4, V=6 fixed-shape message-passing step.
// Single warp, per-k lane specialization (best wall-time variant, R4):
//   lanes 0..15  : tasks (k=0) and (k=2) for (a,f)=(t>>2, t&3)  [fa via float4]
//   lanes 16..31 : task  (k=1) for (a,f)                         [fa scalar]
// All static-address operands (fa_n, FN, VN, w0, m, n) go straight to
// registers at entry; only IVF (dynamic gather) and IFV (exchange) use SMEM.
// Two __syncwarp total; tree-structured dot products; scalar 3x32 epilogue.
//
// Input order: [0]num_M [1]num_FN [2]num_VN [3]IVF(4x4x6 f32)
//              [4]VN_index(2x6 i32) [5]m(i32) [6]n(i32)
//              [7]FN_index(4x3 i32) [8]fa_n(4x4x4x4 f32) [9]w0(4x4x6 f32)
// Output: 4x4x6 f32.

#define M_ 4
#define F_ 4
#define V_ 6
#define FV (F_ * V_)   // 24

__global__ void __launch_bounds__(32, 1)
mpa_kernel(const float* __restrict__ IVF,
           const int*   __restrict__ VN_index,
           const int*   __restrict__ m_ptr,
           const int*   __restrict__ n_ptr,
           const int*   __restrict__ FN_index,
           const float* __restrict__ fa_n,
           const float* __restrict__ w0,
           float*       __restrict__ out) {
    __shared__ float s_IVF[M_ * FV];   // [a*24 + f*6 + v]
    __shared__ float s_IFV[M_ * FV];

    const int t = threadIdx.x;          // 0..31
    const bool lo = (t < 16);
    const int u = lo ? t : (t - 16);
    const int a = (u >> 2) & 3;
    const int f = u & 3;

    // ================= stage: every global load issued up front ==============
    if (t < 24) ((float4*)s_IVF)[t] = ((const float4*)IVF)[t];
    // zero IFV (scatter fills only 48 of 96)
    s_IFV[t] = 0.0f; s_IFV[t + 32] = 0.0f; s_IFV[t + 64] = 0.0f;

    const int mm = m_ptr[0];
    const int nn = n_ptr[0];

    // output-phase operands (static per-thread)
    float rw[3]; int vva[3], vvb[3];
    #pragma unroll
    for (int j = 0; j < 3; j++) {
        int idx = t + j * 32;
        int v = idx % V_;
        rw[j]  = w0[idx];
        vva[j] = VN_index[v];
        vvb[j] = VN_index[V_ + v];
    }

    // FN columns for this lane's f (static addresses)
    const int col0 = FN_index[f * 3 + 0];
    const int col1 = FN_index[f * 3 + 1];
    const int col2 = FN_index[f * 3 + 2];

    // fa coefficients (static addresses; issue now, consume after sync)
    const float4* fa4 = (const float4*)fa_n;
    float4 q[4], r[4];      // lanes<16: q[c]=fa[f][c][a][.b]  r[b]=fa[f][a][b][.c]
    float  fvs[16];         // lanes>=16: fvs[b*4+c]=fa[f][c][b][a]
    if (lo) {
        #pragma unroll
        for (int c = 0; c < 4; c++) q[c] = fa4[f * 16 + c * 4 + a];
        #pragma unroll
        for (int b = 0; b < 4; b++) r[b] = fa4[f * 16 + a * 4 + b];
    } else {
        #pragma unroll
        for (int b = 0; b < 4; b++)
            #pragma unroll
            for (int c = 0; c < 4; c++)
                fvs[b * 4 + c] = __ldg(&fa_n[f * 64 + c * 16 + b * 4 + a]);
    }

    __syncwarp();

    // ================= contraction + scatter =================================
    //  k=0: A0[a,f]=Σ_{b,c} g1[b]g2[c] fa[f][c][a][b] -> IFV[a,f,col0]
    //  k=1: A1[a,f]=Σ_{b,c} g0[b]g2[c] fa[f][c][b][a] -> IFV[a,f,col1]
    //  k=2: A2[a,f]=Σ_{b,c} g0[b]g1[c] fa[f][a][b][c] -> IFV[a,f,col2]
    const int gbase = f * V_;
    if (lo) {
        float g0[4], g1[4], g2[4];
        #pragma unroll
        for (int b = 0; b < 4; b++) {
            g0[b] = s_IVF[b * FV + gbase + col0];
            g1[b] = s_IVF[b * FV + gbase + col1];
            g2[b] = s_IVF[b * FV + gbase + col2];
        }
        float d0 = fmaf(g1[3], q[0].w, fmaf(g1[2], q[0].z, fmaf(g1[1], q[0].y, g1[0] * q[0].x)));
        float d1 = fmaf(g1[3], q[1].w, fmaf(g1[2], q[1].z, fmaf(g1[1], q[1].y, g1[0] * q[1].x)));
        float d2 = fmaf(g1[3], q[2].w, fmaf(g1[2], q[2].z, fmaf(g1[1], q[2].y, g1[0] * q[2].x)));
        float d3 = fmaf(g1[3], q[3].w, fmaf(g1[2], q[3].z, fmaf(g1[1], q[3].y, g1[0] * q[3].x)));
        float acc0 = fmaf(g2[3], d3, fmaf(g2[2], d2, fmaf(g2[1], d1, g2[0] * d0)));
        float e0 = fmaf(g1[3], r[0].w, fmaf(g1[2], r[0].z, fmaf(g1[1], r[0].y, g1[0] * r[0].x)));
        float e1 = fmaf(g1[3], r[1].w, fmaf(g1[2], r[1].z, fmaf(g1[1], r[1].y, g1[0] * r[1].x)));
        float e2 = fmaf(g1[3], r[2].w, fmaf(g1[2], r[2].z, fmaf(g1[1], r[2].y, g1[0] * r[2].x)));
        float e3 = fmaf(g1[3], r[3].w, fmaf(g1[2], r[3].z, fmaf(g1[1], r[3].y, g1[0] * r[3].x)));
        float acc2 = fmaf(g0[3], e3, fmaf(g0[2], e2, fmaf(g0[1], e1, g0[0] * e0)));
        s_IFV[a * FV + gbase + col0] = acc0;   // distinct cols: no collisions
        s_IFV[a * FV + gbase + col2] = acc2;
    } else {
        float g0[4], g2[4];
        #pragma unroll
        for (int b = 0; b < 4; b++) {
            g0[b] = s_IVF[b * FV + gbase + col0];
            g2[b] = s_IVF[b * FV + gbase + col2];
        }
        float acc1 = 0.0f;
        #pragma unroll
        for (int b = 0; b < 4; b++) {
            float d = fmaf(g2[3], fvs[b * 4 + 3],
                      fmaf(g2[2], fvs[b * 4 + 2],
                      fmaf(g2[1], fvs[b * 4 + 1], g2[0] * fvs[b * 4 + 0])));
            acc1 = fmaf(g0[b], d, acc1);
        }
        s_IFV[a * FV + gbase + col1] = acc1;
    }

    __syncwarp();

    // ================= output (mean fused: IFV/sum == (IFV/M)/(sum/M)) =======
    const bool doUpdate = (mm < nn);
    #pragma unroll
    for (int j = 0; j < 3; j++) {
        int idx = t + j * 32;
        int oa = idx / FV;
        int rr = idx % FV;
        int of = rr / V_;
        int ov = rr % V_;
        float val = s_IVF[idx];
        if (doUpdate) {
            int va = vva[j], vb = vvb[j];
            int src = (of == va) ? vb : (of == vb) ? va : -1;
            if (src >= 0) {
                int base = src * V_ + ov;
                float sum = s_IFV[base] + s_IFV[base + FV] +
                            s_IFV[base + 2 * FV] + s_IFV[base + 3 * FV];
                val = __fdividef(s_IFV[oa * FV + base], sum);
            }
            val *= rw[j];
        }
        out[idx] = val;
    }
}

extern "C" void kernel_launch(void* const* d_in, const int* in_sizes, int n_in,
                              void* d_out, int out_size) {
    const float* IVF      = (const float*)d_in[3];
    const int*   VN_index = (const int*)  d_in[4];
    const int*   m_ptr    = (const int*)  d_in[5];
    const int*   n_ptr    = (const int*)  d_in[6];
    const int*   FN_index = (const int*)  d_in[7];
    const float* fa_n     = (const float*)d_in[8];
    const float* w0       = (const float*)d_in[9];
    float* out = (float*)d_out;

    mpa_kernel<<<1, 32>>>(IVF, VN_index, m_ptr, n_ptr, FN_index, fa_n, w0, out);
}